// round 14
// baseline (speedup 1.0000x reference)
#include <cuda_runtime.h>
#include <cuda_fp16.h>
#include <math.h>
#include <stdint.h>

#define N_TOK 2048
#define HID   2048
#define H     32
#define DK    128
#define PROJ  4096

// ---------------- fp32 scratch ---------------------------------------------
__device__ float g_XQ[N_TOK * PROJ];   // pre-conv q; later reused as Gate
__device__ float g_XK[N_TOK * PROJ];
__device__ float g_XV[N_TOK * PROJ];
__device__ float g_Q [N_TOK * PROJ];
__device__ float g_Kb[N_TOK * PROJ];
__device__ float g_Vb[N_TOK * PROJ];
__device__ float g_EG[N_TOK * PROJ];
__device__ float g_O [N_TOK * PROJ];
__device__ float g_FG[N_TOK * 256];    // [f | ga] low-rank concat
__device__ float g_beta[N_TOK * H];

// ---------------- fp16 scratch ----------------------------------------------
__device__ __half s_hsH[N_TOK*HID];
__device__ __half s_WqH[PROJ*HID],  s_WqL[PROJ*HID];
__device__ __half s_WkH[PROJ*HID],  s_WkL[PROJ*HID];
__device__ __half s_WvH[PROJ*HID],  s_WvL[PROJ*HID];
__device__ __half s_WoH[HID*PROJ],  s_WoL[HID*PROJ];
__device__ __half s_WfgH[256*HID],  s_WfgL[256*HID];   // [Wfa;Wga]
__device__ __half s_WfbH[PROJ*DK],  s_WfbL[PROJ*DK];
__device__ __half s_WgbH[PROJ*DK],  s_WgbL[PROJ*DK];
__device__ __half s_FGH[N_TOK*256];
__device__ __half s_ONH[N_TOK*PROJ];

// ---------------- PTX helpers ----------------------------------------------
__device__ __forceinline__ uint32_t smem_u32(const void* p) {
    uint32_t a;
    asm("{ .reg .u64 t; cvta.to.shared.u64 t, %1; cvt.u32.u64 %0, t; }" : "=r"(a) : "l"(p));
    return a;
}
__device__ __forceinline__ void cp_async16(uint32_t s, const void* g) {
    asm volatile("cp.async.cg.shared.global [%0], [%1], 16;" :: "r"(s), "l"(g));
}
#define CP_COMMIT() asm volatile("cp.async.commit_group;" ::: "memory")
#define CP_WAIT(N)  asm volatile("cp.async.wait_group %0;" :: "n"(N) : "memory")

#define LDSM4(r, a) \
    asm volatile("ldmatrix.sync.aligned.m8n8.x4.shared.b16 {%0,%1,%2,%3}, [%4];" \
        : "=r"((r)[0]),"=r"((r)[1]),"=r"((r)[2]),"=r"((r)[3]) : "r"(a))

__device__ __forceinline__ void mma16816h(float* c, const uint32_t* a,
                                          uint32_t b0, uint32_t b1) {
    asm volatile("mma.sync.aligned.m16n8k16.row.col.f32.f16.f16.f32 "
        "{%0,%1,%2,%3}, {%4,%5,%6,%7}, {%8,%9}, {%0,%1,%2,%3};"
        : "+f"(c[0]), "+f"(c[1]), "+f"(c[2]), "+f"(c[3])
        : "r"(a[0]), "r"(a[1]), "r"(a[2]), "r"(a[3]), "r"(b0), "r"(b1));
}

// packed f32x2 ops (Blackwell dual-FMA pipe)
#define FMA2(d, a, b, c) \
    asm("fma.rn.f32x2 %0, %1, %2, %3;" : "=l"(d) : "l"(a), "l"(b), "l"(c))
#define MUL2(d, a, b) \
    asm("mul.rn.f32x2 %0, %1, %2;" : "=l"(d) : "l"(a), "l"(b))
__device__ __forceinline__ unsigned long long pack2(float a, float b) {
    unsigned long long r;
    asm("mov.b64 %0, {%1, %2};" : "=l"(r) : "f"(a), "f"(b));
    return r;
}
__device__ __forceinline__ float sum2(unsigned long long x) {
    float a, b;
    asm("mov.b64 {%0, %1}, %2;" : "=f"(a), "=f"(b) : "l"(x));
    return a + b;
}

// ---------------- fp16 2-pass tensor GEMM (mma.sync) -------------------------
// C[M,N] = A[M,K] @ ((BH+BL)[N,K])^T, fp32 acc, 2 passes (A*Bh + A*Bl).
// CTA 128x128, 4 warps (warp tile 64x64), 2 CTAs/SM co-resident.
// BK=32, 3-stage cp.async pipeline, rows padded to 80B (conflict-free ldsm).
// Inner loop issues ALL hh MMAs then ALL hl MMAs: accumulator reuse distance
// = 32 MMAs, hiding HMMA latency (was 2 back-to-back on the same acc).
#define ROWB    80
#define OFF_B0  10240
#define OFF_B1  20480
#define STG     30720
#define GEMM_SMEM (3 * STG + 128)

__device__ __forceinline__ void load_chunk32(
    uint32_t stage, const __half* A, const __half* BH, const __half* BL,
    int brow, int bcol, int lda, int ldb, int k0, int tid)
{
    #pragma unroll
    for (int it = 0; it < 12; it++) {
        int g   = tid + it * 128;          // 1536 x 16B segments
        int row = g >> 2;
        int c   = g & 3;
        const __half* src;
        uint32_t dst;
        int grow, ld;
        if (row < 128)      { int r = row;       src = A;  grow = brow + r; ld = lda; dst = stage +          r * ROWB; }
        else if (row < 256) { int r = row - 128; src = BH; grow = bcol + r; ld = ldb; dst = stage + OFF_B0 + r * ROWB; }
        else                { int r = row - 256; src = BL; grow = bcol + r; ld = ldb; dst = stage + OFF_B1 + r * ROWB; }
        cp_async16(dst + c * 16, src + (size_t)grow * ld + k0 + c * 8);
    }
    CP_COMMIT();
}

__global__ void __launch_bounds__(128, 2)
mma_gemm(const __half* __restrict__ A, const __half* __restrict__ BH,
         const __half* __restrict__ BL, float* __restrict__ C,
         int K, int lda, int ldb, int ldc)
{
    extern __shared__ char dsm[];
    const uint32_t base = (smem_u32(dsm) + 127u) & ~127u;
    const int tid = threadIdx.x, wid = tid >> 5, lane = tid & 31;
    const int brow = blockIdx.y * 128, bcol = blockIdx.x * 128;
    const int wm = wid & 1, wn = wid >> 1;          // warp tile 64(M) x 64(N)

    float acc[4][8][4];
    #pragma unroll
    for (int i = 0; i < 4; i++)
        #pragma unroll
        for (int j = 0; j < 8; j++)
            #pragma unroll
            for (int r = 0; r < 4; r++) acc[i][j][r] = 0.f;

    const int nch = K / 32;
    load_chunk32(base,       A, BH, BL, brow, bcol, lda, ldb, 0,  tid);
    if (nch > 1)
        load_chunk32(base + STG, A, BH, BL, brow, bcol, lda, ldb, 32, tid);

    const uint32_t aoff = (uint32_t)((wm * 64 + (lane & 15)) * ROWB + ((lane >> 4) & 1) * 16);
    const uint32_t boff = (uint32_t)(OFF_B0 + (wn * 64 + (lane & 7)) * ROWB + (lane >> 3) * 16);

    for (int i = 0; i < nch; i++) {
        if (i + 1 < nch) { CP_WAIT(1); } else { CP_WAIT(0); }
        __syncthreads();
        const uint32_t st = base + (uint32_t)(i % 3) * STG;

        if (i + 2 < nch)
            load_chunk32(base + (uint32_t)((i + 2) % 3) * STG,
                         A, BH, BL, brow, bcol, lda, ldb, (i + 2) * 32, tid);

        // B fragments (hi and lo) for the whole 32-K chunk
        uint32_t bh[8][4], bl[8][4];
        #pragma unroll
        for (int j = 0; j < 8; j++) {
            uint32_t ba = st + boff + (uint32_t)(j * 8 * ROWB);
            LDSM4(bh[j], ba);
            LDSM4(bl[j], ba + (OFF_B1 - OFF_B0));
        }

        #pragma unroll
        for (int ks = 0; ks < 2; ks++) {
            uint32_t ah[4][4];
            #pragma unroll
            for (int mi = 0; mi < 4; mi++) {
                uint32_t aa = st + aoff + (uint32_t)(mi * 16 * ROWB + ks * 32);
                LDSM4(ah[mi], aa);
            }
            // pass 1: all hi MMAs (32 independent accumulator tiles)
            #pragma unroll
            for (int mi = 0; mi < 4; mi++)
                #pragma unroll
                for (int j = 0; j < 8; j++)
                    mma16816h(acc[mi][j], ah[mi], bh[j][2*ks], bh[j][2*ks+1]);
            // pass 2: all lo MMAs (acc reuse distance = 32 MMAs)
            #pragma unroll
            for (int mi = 0; mi < 4; mi++)
                #pragma unroll
                for (int j = 0; j < 8; j++)
                    mma16816h(acc[mi][j], ah[mi], bl[j][2*ks], bl[j][2*ks+1]);
        }
    }

    const int tg = lane >> 2, tt = lane & 3;
    #pragma unroll
    for (int mi = 0; mi < 4; mi++) {
        const int row0 = brow + wm * 64 + mi * 16 + tg;
        #pragma unroll
        for (int j = 0; j < 8; j++) {
            const int col = bcol + wn * 64 + j * 8 + tt * 2;
            *(float2*)(C + (size_t)row0       * ldc + col) = make_float2(acc[mi][j][0], acc[mi][j][1]);
            *(float2*)(C + (size_t)(row0 + 8) * ldc + col) = make_float2(acc[mi][j][2], acc[mi][j][3]);
        }
    }
}

// ---------------- fp32 -> fp16 single convert, vectorized x4 -----------------
__global__ void __launch_bounds__(256)
cvt_half(const float* __restrict__ x, __half* __restrict__ h, int n)
{
    int i = (blockIdx.x * 256 + threadIdx.x) * 4;
    if (i >= n) return;
    float4 v = *(const float4*)(x + i);
    *(__half2*)(h + i)     = __floats2half2_rn(v.x, v.y);
    *(__half2*)(h + i + 2) = __floats2half2_rn(v.z, v.w);
}

// ---------------- fp32 -> (hi,lo) fp16 split, vectorized x4 ------------------
__global__ void __launch_bounds__(256)
cvt_split(const float* __restrict__ x, __half* __restrict__ h,
          __half* __restrict__ l, int n)
{
    int i = (blockIdx.x * 256 + threadIdx.x) * 4;
    if (i >= n) return;
    float4 v = *(const float4*)(x + i);
    __half h0 = __float2half_rn(v.x), h1 = __float2half_rn(v.y);
    __half h2 = __float2half_rn(v.z), h3 = __float2half_rn(v.w);
    *(__half2*)(h + i)     = __half2(h0, h1);
    *(__half2*)(h + i + 2) = __half2(h2, h3);
    *(__half2*)(l + i)     = __half2(__float2half_rn(v.x - __half2float(h0)),
                                     __float2half_rn(v.y - __half2float(h1)));
    *(__half2*)(l + i + 2) = __half2(__float2half_rn(v.z - __half2float(h2)),
                                     __float2half_rn(v.w - __half2float(h3)));
}

// concat + split: rows 0-127 = Wfa, 128-255 = Wga, both [128, HID]
__global__ void __launch_bounds__(256)
cvt_concat_split(const float* __restrict__ Wfa, const float* __restrict__ Wga,
                 __half* __restrict__ h, __half* __restrict__ l)
{
    int i = (blockIdx.x * 256 + threadIdx.x) * 4;     // over 256*HID
    int r = i >> 11, c = i & (HID - 1);
    const float* src = (r < 128) ? (Wfa + (size_t)r * HID + c)
                                 : (Wga + (size_t)(r - 128) * HID + c);
    float4 v = *(const float4*)src;
    __half h0 = __float2half_rn(v.x), h1 = __float2half_rn(v.y);
    __half h2 = __float2half_rn(v.z), h3 = __float2half_rn(v.w);
    *(__half2*)(h + i)     = __half2(h0, h1);
    *(__half2*)(h + i + 2) = __half2(h2, h3);
    *(__half2*)(l + i)     = __half2(__float2half_rn(v.x - __half2float(h0)),
                                     __float2half_rn(v.y - __half2float(h1)));
    *(__half2*)(l + i + 2) = __half2(__float2half_rn(v.z - __half2float(h2)),
                                     __float2half_rn(v.w - __half2float(h3)));
}

// ---------------- block reduce over 128 threads ------------------------------
__device__ __forceinline__ float blockReduceSum128(float v) {
    __shared__ float sh[4];
    #pragma unroll
    for (int o = 16; o; o >>= 1) v += __shfl_xor_sync(0xffffffffu, v, o);
    if ((threadIdx.x & 31) == 0) sh[threadIdx.x >> 5] = v;
    __syncthreads();
    return sh[0] + sh[1] + sh[2] + sh[3];
}

// ---------------- causal conv(K=4) + SiLU (+ optional L2 norm) ---------------
template<int MODE>  // 0=v, 1=k (l2), 2=q (l2 * dk^-0.5)
__global__ void __launch_bounds__(128)
conv_silu(const float* __restrict__ X, const float* __restrict__ W,
          float* __restrict__ Y)
{
    const int n = blockIdx.x, hh = blockIdx.y, t = threadIdx.x;
    const int c = hh * DK + t;
    const float4 w = *(const float4*)(W + (size_t)c * 4);
    float x0 = (n >= 3) ? X[(size_t)(n-3)*PROJ + c] : 0.f;
    float x1 = (n >= 2) ? X[(size_t)(n-2)*PROJ + c] : 0.f;
    float x2 = (n >= 1) ? X[(size_t)(n-1)*PROJ + c] : 0.f;
    float x3 = X[(size_t)n*PROJ + c];
    float y = x0*w.x + x1*w.y + x2*w.z + x3*w.w;
    y = y / (1.f + expf(-y));
    if (MODE == 0) { Y[(size_t)n*PROJ + c] = y; return; }
    float ss = blockReduceSum128(y * y);
    float sc = rsqrtf(ss + 1e-6f);
    if (MODE == 2) sc *= 0.08838834764831845f;
    Y[(size_t)n*PROJ + c] = y * sc;
}

// ---------------- decay gate: EG = exp(-exp(A_log[h]) * softplus(F + bias)) --
__global__ void decay_kernel(float* __restrict__ F, const float* __restrict__ dtb,
                             const float* __restrict__ A_log)
{
    size_t idx = (size_t)blockIdx.x * blockDim.x + threadIdx.x;
    int c = (int)(idx % PROJ);
    int h = c / DK;
    float x = F[idx] + dtb[c];
    float sp = (x > 20.f) ? x : log1pf(expf(x));
    F[idx] = expf(-expf(A_log[h]) * sp);
}

// ---------------- beta = sigmoid(hidden @ Wb^T) ------------------------------
__global__ void __launch_bounds__(256)
beta_kernel(const float* __restrict__ Xh, const float* __restrict__ Wb,
            float* __restrict__ Beta)
{
    const int warp = threadIdx.x >> 5, lane = threadIdx.x & 31;
    const int n = blockIdx.x;
    const int h = blockIdx.y * 8 + warp;
    const float* x = Xh + (size_t)n * HID;
    const float* w = Wb + (size_t)h * HID;
    float s = 0.f;
    for (int i = lane; i < HID; i += 32) s += x[i] * w[i];
    #pragma unroll
    for (int o = 16; o; o >>= 1) s += __shfl_xor_sync(0xffffffffu, s, o);
    if (lane == 0) Beta[(size_t)n * H + h] = 1.f / (1.f + expf(-s));
}

// ---------------- delta-rule scan v3 ----------------------------------------
// grid (4 v-blocks, 32 heads), 128 threads. thread: v = t>>2, ks = t&3;
// owns S[ks*32+j][v] as 16 packed f32x2. 4-way split accumulators shorten
// the two serial FMA chains (16 -> 4 deep). One __syncthreads per step.
__global__ void __launch_bounds__(128)
scan_kernel(const float* __restrict__ Q, const float* __restrict__ Kb,
            const float* __restrict__ Vb, const float* __restrict__ EG,
            const float* __restrict__ Beta, float* __restrict__ O)
{
    const int vb = blockIdx.x, h = blockIdx.y;
    const int t = threadIdx.x;
    const int v = t >> 2, ks = t & 3;
    __shared__ float sk[2][144], sq[2][144], se[2][144];

    unsigned long long S2[16];
    #pragma unroll
    for (int j = 0; j < 16; j++) S2[j] = 0ull;

    const size_t hb = (size_t)h * DK;
    const size_t vboff = hb + (size_t)vb * 32;
    const int slot = (t >> 5) * 36 + (t & 31);

    float rk = Kb[hb + t], rq = Q[hb + t], re = EG[hb + t];
    float rv = Vb[vboff + v], rb = Beta[h];
    sk[0][slot] = rk; sq[0][slot] = rq; se[0][slot] = re;
    float curv = rv, curb = rb;

    rk = Kb[PROJ + hb + t]; rq = Q[PROJ + hb + t]; re = EG[PROJ + hb + t];
    rv = Vb[PROJ + vboff + v]; rb = Beta[H + h];
    __syncthreads();

    for (int n = 0; n < N_TOK; n++) {
        const int cur = n & 1;
        float nv = rv, nb = rb;
        if (n + 1 < N_TOK) {
            sk[cur ^ 1][slot] = rk; sq[cur ^ 1][slot] = rq; se[cur ^ 1][slot] = re;
        }
        if (n + 2 < N_TOK) {
            size_t b = (size_t)(n + 2) * PROJ;
            rk = Kb[b + hb + t]; rq = Q[b + hb + t]; re = EG[b + hb + t];
            rv = Vb[b + vboff + v]; rb = Beta[(size_t)(n + 2) * H + h];
        }

        const float* kp = &sk[cur][ks * 36];
        const float* ep = &se[cur][ks * 36];
        const float* qp = &sq[cur][ks * 36];

        unsigned long long k2[16];
        unsigned long long kva = 0ull, kvb = 0ull, kvc = 0ull, kvd = 0ull;
        #pragma unroll
        for (int j = 0; j < 16; j += 4) {
            k2[j]   = *(const unsigned long long*)(kp + 2*j);
            k2[j+1] = *(const unsigned long long*)(kp + 2*j + 2);
            k2[j+2] = *(const unsigned long long*)(kp + 2*j + 4);
            k2[j+3] = *(const unsigned long long*)(kp + 2*j + 6);
            unsigned long long e0 = *(const unsigned long long*)(ep + 2*j);
            unsigned long long e1 = *(const unsigned long long*)(ep + 2*j + 2);
            unsigned long long e2 = *(const unsigned long long*)(ep + 2*j + 4);
            unsigned long long e3 = *(const unsigned long long*)(ep + 2*j + 6);
            MUL2(S2[j],   S2[j],   e0);  FMA2(kva, k2[j],   S2[j],   kva);
            MUL2(S2[j+1], S2[j+1], e1);  FMA2(kvb, k2[j+1], S2[j+1], kvb);
            MUL2(S2[j+2], S2[j+2], e2);  FMA2(kvc, k2[j+2], S2[j+2], kvc);
            MUL2(S2[j+3], S2[j+3], e3);  FMA2(kvd, k2[j+3], S2[j+3], kvd);
        }
        float kv = sum2(kva) + sum2(kvb) + (sum2(kvc) + sum2(kvd));
        kv += __shfl_xor_sync(0xffffffffu, kv, 1);
        kv += __shfl_xor_sync(0xffffffffu, kv, 2);
        float delta = (curv - kv) * curb;
        unsigned long long d2 = pack2(delta, delta);

        unsigned long long oa = 0ull, ob = 0ull, oc = 0ull, od = 0ull;
        #pragma unroll
        for (int j = 0; j < 16; j += 4) {
            unsigned long long q0 = *(const unsigned long long*)(qp + 2*j);
            unsigned long long q1 = *(const unsigned long long*)(qp + 2*j + 2);
            unsigned long long q2 = *(const unsigned long long*)(qp + 2*j + 4);
            unsigned long long q3 = *(const unsigned long long*)(qp + 2*j + 6);
            FMA2(S2[j],   k2[j],   d2, S2[j]);    FMA2(oa, q0, S2[j],   oa);
            FMA2(S2[j+1], k2[j+1], d2, S2[j+1]);  FMA2(ob, q1, S2[j+1], ob);
            FMA2(S2[j+2], k2[j+2], d2, S2[j+2]);  FMA2(oc, q2, S2[j+2], oc);
            FMA2(S2[j+3], k2[j+3], d2, S2[j+3]);  FMA2(od, q3, S2[j+3], od);
        }
        float op = sum2(oa) + sum2(ob) + (sum2(oc) + sum2(od));
        op += __shfl_xor_sync(0xffffffffu, op, 1);
        op += __shfl_xor_sync(0xffffffffu, op, 2);
        if (ks == 0) O[(size_t)n * PROJ + vboff + v] = op;

        curv = nv; curb = nb;
        __syncthreads();
    }
}

// ---------------- gated RMSNorm -> fp16 --------------------------------------
__global__ void __launch_bounds__(128)
norm_gate(const float* __restrict__ O, const float* __restrict__ Gate,
          const float* __restrict__ onw, __half* __restrict__ oh)
{
    const int n = blockIdx.x, hh = blockIdx.y, t = threadIdx.x;
    const size_t idx = (size_t)n * PROJ + hh * DK + t;
    float o = O[idx];
    float ms = blockReduceSum128(o * o) * (1.f / DK);
    float r = o * rsqrtf(ms + 1e-5f);
    float g = Gate[idx];
    float y = r * onw[t] / (1.f + expf(-g));
    oh[idx] = __float2half_rn(y);
}

// ---------------- launch -----------------------------------------------------
extern "C" void kernel_launch(void* const* d_in, const int* in_sizes, int n_in,
                              void* d_out, int out_size)
{
    const float* hs      = (const float*)d_in[0];
    const float* Wq      = (const float*)d_in[1];
    const float* Wk      = (const float*)d_in[2];
    const float* Wv      = (const float*)d_in[3];
    const float* conv_q  = (const float*)d_in[4];
    const float* conv_k  = (const float*)d_in[5];
    const float* conv_v  = (const float*)d_in[6];
    const float* Wfa     = (const float*)d_in[7];
    const float* Wfb     = (const float*)d_in[8];
    const float* dt_bias = (const float*)d_in[9];
    const float* Wb      = (const float*)d_in[10];
    const float* A_log   = (const float*)d_in[11];
    const float* Wga     = (const float*)d_in[12];
    const float* Wgb     = (const float*)d_in[13];
    const float* onorm_w = (const float*)d_in[14];
    const float* Wo      = (const float*)d_in[15];
    float* out = (float*)d_out;

    float *pXQ, *pXK, *pXV, *pQ, *pK, *pV, *pEG, *pO, *pFG, *pBeta;
    cudaGetSymbolAddress((void**)&pXQ, g_XQ);
    cudaGetSymbolAddress((void**)&pXK, g_XK);
    cudaGetSymbolAddress((void**)&pXV, g_XV);
    cudaGetSymbolAddress((void**)&pQ,  g_Q);
    cudaGetSymbolAddress((void**)&pK,  g_Kb);
    cudaGetSymbolAddress((void**)&pV,  g_Vb);
    cudaGetSymbolAddress((void**)&pEG, g_EG);
    cudaGetSymbolAddress((void**)&pO,  g_O);
    cudaGetSymbolAddress((void**)&pFG, g_FG);
    cudaGetSymbolAddress((void**)&pBeta, g_beta);

    __half *hsH,*WqH,*WqL,*WkH,*WkL,*WvH,*WvL,*WoH,*WoL;
    __half *WfgH,*WfgL,*WfbH,*WfbL,*WgbH,*WgbL,*FGH,*ONH;
    cudaGetSymbolAddress((void**)&hsH, s_hsH);
    cudaGetSymbolAddress((void**)&WqH, s_WqH);  cudaGetSymbolAddress((void**)&WqL, s_WqL);
    cudaGetSymbolAddress((void**)&WkH, s_WkH);  cudaGetSymbolAddress((void**)&WkL, s_WkL);
    cudaGetSymbolAddress((void**)&WvH, s_WvH);  cudaGetSymbolAddress((void**)&WvL, s_WvL);
    cudaGetSymbolAddress((void**)&WoH, s_WoH);  cudaGetSymbolAddress((void**)&WoL, s_WoL);
    cudaGetSymbolAddress((void**)&WfgH, s_WfgH);cudaGetSymbolAddress((void**)&WfgL, s_WfgL);
    cudaGetSymbolAddress((void**)&WfbH, s_WfbH);cudaGetSymbolAddress((void**)&WfbL, s_WfbL);
    cudaGetSymbolAddress((void**)&WgbH, s_WgbH);cudaGetSymbolAddress((void**)&WgbL, s_WgbL);
    cudaGetSymbolAddress((void**)&FGH, s_FGH);
    cudaGetSymbolAddress((void**)&ONH, s_ONH);

    cudaFuncSetAttribute(mma_gemm, cudaFuncAttributeMaxDynamicSharedMemorySize, GEMM_SMEM);

    auto grid4 = [](int n) { return dim3((n / 4 + 255) / 256); };

    const dim3 gBig(PROJ/128, N_TOK/128);   // 32 x 16
    const dim3 gOut(HID/128,  N_TOK/128);   // 16 x 16
    const dim3 gFG (256/128,  N_TOK/128);   //  2 x 16
    const dim3 gCh (N_TOK, H);

    // conversions for Q/K GEMMs (keeps a mma_gemm in the profiled launch slot)
    cvt_half<<<grid4(N_TOK*HID), 256>>>(hs, hsH, N_TOK*HID);
    cvt_split<<<grid4(PROJ*HID), 256>>>(Wq, WqH, WqL, PROJ*HID);
    cvt_split<<<grid4(PROJ*HID), 256>>>(Wk, WkH, WkL, PROJ*HID);

    mma_gemm<<<gBig, 128, GEMM_SMEM>>>(hsH, WqH, WqL, pXQ, HID, HID, HID, PROJ);
    cvt_split<<<grid4(PROJ*HID), 256>>>(Wv, WvH, WvL, PROJ*HID);
    mma_gemm<<<gBig, 128, GEMM_SMEM>>>(hsH, WkH, WkL, pXK, HID, HID, HID, PROJ);
    cvt_split<<<grid4(HID*PROJ), 256>>>(Wo, WoH, WoL, HID*PROJ);
    mma_gemm<<<gBig, 128, GEMM_SMEM>>>(hsH, WvH, WvL, pXV, HID, HID, HID, PROJ);

    cvt_split<<<grid4(PROJ*DK), 256>>>(Wfb, WfbH, WfbL, PROJ*DK);
    cvt_split<<<grid4(PROJ*DK), 256>>>(Wgb, WgbH, WgbL, PROJ*DK);
    cvt_concat_split<<<grid4(256*HID), 256>>>(Wfa, Wga, WfgH, WfgL);

    // conv + silu (+ norms)
    conv_silu<2><<<gCh, 128>>>(pXQ, conv_q, pQ);
    conv_silu<1><<<gCh, 128>>>(pXK, conv_k, pK);
    conv_silu<0><<<gCh, 128>>>(pXV, conv_v, pV);

    // low-rank concat: FG = hs @ [Wfa;Wga]^T -> [N, 256]
    mma_gemm<<<gFG, 128, GEMM_SMEM>>>(hsH, WfgH, WfgL, pFG, HID, HID, HID, 256);
    cvt_half<<<grid4(N_TOK*256), 256>>>(pFG, FGH, N_TOK*256);

    // decay chain: EG = FG[:, :128] @ Wfb^T -> exp(g)
    mma_gemm<<<gBig, 128, GEMM_SMEM>>>(FGH, WfbH, WfbL, pEG, DK, 256, DK, PROJ);
    decay_kernel<<<(N_TOK*(size_t)PROJ)/256, 256>>>(pEG, dt_bias, A_log);

    // gate: Gate = FG[:, 128:] @ Wgb^T (reuse g_XQ)
    mma_gemm<<<gBig, 128, GEMM_SMEM>>>(FGH + 128, WgbH, WgbL, pXQ, DK, 256, DK, PROJ);

    // beta
    beta_kernel<<<dim3(N_TOK, 4), 256>>>(hs, Wb, pBeta);

    // recurrent delta-rule scan
    scan_kernel<<<dim3(4, H), 128>>>(pQ, pK, pV, pEG, pBeta, pO);

    // gated RMSNorm -> fp16
    norm_gate<<<gCh, 128>>>(pO, pXQ, onorm_w, ONH);

    // output projection
    mma_gemm<<<gOut, 128, GEMM_SMEM>>>(ONH, WoH, WoL, out, PROJ, PROJ, PROJ, HID);
}

// round 15
// speedup vs baseline: 1.0637x; 1.0637x over previous
#include <cuda_runtime.h>
#include <cuda_fp16.h>
#include <math.h>
#include <stdint.h>

#define N_TOK 2048
#define HID   2048
#define H     32
#define DK    128
#define PROJ  4096
#define NCAT  (3*PROJ + 256)    // Wq | Wk | Wv | [Wfa;Wga]

// ---------------- fp32 scratch ---------------------------------------------
__device__ float g_XCAT[N_TOK * NCAT];  // fused qkv+fg projection output
__device__ float g_XQ[N_TOK * PROJ];    // Gate buffer
__device__ float g_Q [N_TOK * PROJ];
__device__ float g_Kb[N_TOK * PROJ];
__device__ float g_Vb[N_TOK * PROJ];
__device__ float g_EG[N_TOK * PROJ];
__device__ float g_O [N_TOK * PROJ];
__device__ float g_beta[N_TOK * H];

// ---------------- fp16 scratch ----------------------------------------------
__device__ __half s_hsH[N_TOK*HID];
__device__ __half s_WcatH[(size_t)NCAT*HID], s_WcatL[(size_t)NCAT*HID];
__device__ __half s_WoH[HID*PROJ],  s_WoL[HID*PROJ];
__device__ __half s_WfbH[PROJ*DK],  s_WfbL[PROJ*DK];
__device__ __half s_WgbH[PROJ*DK],  s_WgbL[PROJ*DK];
__device__ __half s_FGH[N_TOK*256];
__device__ __half s_ONH[N_TOK*PROJ];

// ---------------- PTX helpers ----------------------------------------------
__device__ __forceinline__ uint32_t smem_u32(const void* p) {
    uint32_t a;
    asm("{ .reg .u64 t; cvta.to.shared.u64 t, %1; cvt.u32.u64 %0, t; }" : "=r"(a) : "l"(p));
    return a;
}
__device__ __forceinline__ void cp_async16(uint32_t s, const void* g) {
    asm volatile("cp.async.cg.shared.global [%0], [%1], 16;" :: "r"(s), "l"(g));
}
#define CP_COMMIT() asm volatile("cp.async.commit_group;" ::: "memory")
#define CP_WAIT(N)  asm volatile("cp.async.wait_group %0;" :: "n"(N) : "memory")

#define LDSM4(r, a) \
    asm volatile("ldmatrix.sync.aligned.m8n8.x4.shared.b16 {%0,%1,%2,%3}, [%4];" \
        : "=r"((r)[0]),"=r"((r)[1]),"=r"((r)[2]),"=r"((r)[3]) : "r"(a))

__device__ __forceinline__ void mma16816h(float* c, const uint32_t* a,
                                          uint32_t b0, uint32_t b1) {
    asm volatile("mma.sync.aligned.m16n8k16.row.col.f32.f16.f16.f32 "
        "{%0,%1,%2,%3}, {%4,%5,%6,%7}, {%8,%9}, {%0,%1,%2,%3};"
        : "+f"(c[0]), "+f"(c[1]), "+f"(c[2]), "+f"(c[3])
        : "r"(a[0]), "r"(a[1]), "r"(a[2]), "r"(a[3]), "r"(b0), "r"(b1));
}

// packed f32x2 ops (Blackwell dual-FMA pipe)
#define FMA2(d, a, b, c) \
    asm("fma.rn.f32x2 %0, %1, %2, %3;" : "=l"(d) : "l"(a), "l"(b), "l"(c))
#define MUL2(d, a, b) \
    asm("mul.rn.f32x2 %0, %1, %2;" : "=l"(d) : "l"(a), "l"(b))
__device__ __forceinline__ unsigned long long pack2(float a, float b) {
    unsigned long long r;
    asm("mov.b64 %0, {%1, %2};" : "=l"(r) : "f"(a), "f"(b));
    return r;
}
__device__ __forceinline__ float sum2(unsigned long long x) {
    float a, b;
    asm("mov.b64 {%0, %1}, %2;" : "=f"(a), "=f"(b) : "l"(x));
    return a + b;
}

// ---------------- fp16 2-pass tensor GEMM (mma.sync) -------------------------
// C[M,N] = A[M,K] @ ((BH+BL)[N,K])^T, fp32 acc, 2 passes (A*Bh + A*Bl).
// CTA 128x128, EIGHT warps (warp tile 64x32) -> 4 MMA-issuing warps per SMSP
// with 2 CTAs/SM co-resident. BK=32, 3-stage cp.async pipeline, 80B rows.
#define ROWB    80
#define OFF_B0  10240
#define OFF_B1  20480
#define STG     30720
#define GEMM_SMEM (3 * STG + 128)

__device__ __forceinline__ void load_chunk32(
    uint32_t stage, const __half* A, const __half* BH, const __half* BL,
    int brow, int bcol, int lda, int ldb, int k0, int tid)
{
    #pragma unroll
    for (int it = 0; it < 6; it++) {
        int g   = tid + it * 256;          // 1536 x 16B segments
        int row = g >> 2;
        int c   = g & 3;
        const __half* src;
        uint32_t dst;
        int grow, ld;
        if (row < 128)      { int r = row;       src = A;  grow = brow + r; ld = lda; dst = stage +          r * ROWB; }
        else if (row < 256) { int r = row - 128; src = BH; grow = bcol + r; ld = ldb; dst = stage + OFF_B0 + r * ROWB; }
        else                { int r = row - 256; src = BL; grow = bcol + r; ld = ldb; dst = stage + OFF_B1 + r * ROWB; }
        cp_async16(dst + c * 16, src + (size_t)grow * ld + k0 + c * 8);
    }
    CP_COMMIT();
}

__global__ void __launch_bounds__(256, 2)
mma_gemm(const __half* __restrict__ A, const __half* __restrict__ BH,
         const __half* __restrict__ BL, float* __restrict__ C,
         int K, int lda, int ldb, int ldc)
{
    extern __shared__ char dsm[];
    const uint32_t base = (smem_u32(dsm) + 127u) & ~127u;
    const int tid = threadIdx.x, wid = tid >> 5, lane = tid & 31;
    const int brow = blockIdx.y * 128, bcol = blockIdx.x * 128;
    const int wm = wid & 1, wn = wid >> 1;          // warp tile 64(M) x 32(N)

    float acc[4][4][4];
    #pragma unroll
    for (int i = 0; i < 4; i++)
        #pragma unroll
        for (int j = 0; j < 4; j++)
            #pragma unroll
            for (int r = 0; r < 4; r++) acc[i][j][r] = 0.f;

    const int nch = K / 32;
    load_chunk32(base,       A, BH, BL, brow, bcol, lda, ldb, 0,  tid);
    if (nch > 1)
        load_chunk32(base + STG, A, BH, BL, brow, bcol, lda, ldb, 32, tid);

    const uint32_t aoff = (uint32_t)((wm * 64 + (lane & 15)) * ROWB + ((lane >> 4) & 1) * 16);
    const uint32_t boff = (uint32_t)(OFF_B0 + (wn * 32 + (lane & 7)) * ROWB + (lane >> 3) * 16);

    for (int i = 0; i < nch; i++) {
        if (i + 1 < nch) { CP_WAIT(1); } else { CP_WAIT(0); }
        __syncthreads();
        const uint32_t st = base + (uint32_t)(i % 3) * STG;

        if (i + 2 < nch)
            load_chunk32(base + (uint32_t)((i + 2) % 3) * STG,
                         A, BH, BL, brow, bcol, lda, ldb, (i + 2) * 32, tid);

        // B fragments (hi and lo) for the whole 32-K chunk
        uint32_t bh[4][4], bl[4][4];
        #pragma unroll
        for (int j = 0; j < 4; j++) {
            uint32_t ba = st + boff + (uint32_t)(j * 8 * ROWB);
            LDSM4(bh[j], ba);
            LDSM4(bl[j], ba + (OFF_B1 - OFF_B0));
        }

        #pragma unroll
        for (int ks = 0; ks < 2; ks++) {
            uint32_t ah[4][4];
            #pragma unroll
            for (int mi = 0; mi < 4; mi++) {
                uint32_t aa = st + aoff + (uint32_t)(mi * 16 * ROWB + ks * 32);
                LDSM4(ah[mi], aa);
            }
            #pragma unroll
            for (int mi = 0; mi < 4; mi++)
                #pragma unroll
                for (int j = 0; j < 4; j++)
                    mma16816h(acc[mi][j], ah[mi], bh[j][2*ks], bh[j][2*ks+1]);
            #pragma unroll
            for (int mi = 0; mi < 4; mi++)
                #pragma unroll
                for (int j = 0; j < 4; j++)
                    mma16816h(acc[mi][j], ah[mi], bl[j][2*ks], bl[j][2*ks+1]);
        }
    }

    const int tg = lane >> 2, tt = lane & 3;
    #pragma unroll
    for (int mi = 0; mi < 4; mi++) {
        const int row0 = brow + wm * 64 + mi * 16 + tg;
        #pragma unroll
        for (int j = 0; j < 4; j++) {
            const int col = bcol + wn * 32 + j * 8 + tt * 2;
            *(float2*)(C + (size_t)row0       * ldc + col) = make_float2(acc[mi][j][0], acc[mi][j][1]);
            *(float2*)(C + (size_t)(row0 + 8) * ldc + col) = make_float2(acc[mi][j][2], acc[mi][j][3]);
        }
    }
}

// ---------------- fp32 -> fp16 single convert, vectorized x4 -----------------
__global__ void __launch_bounds__(256)
cvt_half(const float* __restrict__ x, __half* __restrict__ h, int n)
{
    int i = (blockIdx.x * 256 + threadIdx.x) * 4;
    if (i >= n) return;
    float4 v = *(const float4*)(x + i);
    *(__half2*)(h + i)     = __floats2half2_rn(v.x, v.y);
    *(__half2*)(h + i + 2) = __floats2half2_rn(v.z, v.w);
}

// strided FG extract: FGH[n,j] = half(XCAT[n, 3*PROJ + j]), j<256
__global__ void __launch_bounds__(256)
cvt_fg(const float* __restrict__ xcat, __half* __restrict__ h)
{
    int i = (blockIdx.x * 256 + threadIdx.x) * 4;   // over N_TOK*256
    int n = i >> 8, j = i & 255;
    float4 v = *(const float4*)(xcat + (size_t)n * NCAT + 3*PROJ + j);
    *(__half2*)(h + i)     = __floats2half2_rn(v.x, v.y);
    *(__half2*)(h + i + 2) = __floats2half2_rn(v.z, v.w);
}

// ---------------- fp32 -> (hi,lo) fp16 split, vectorized x4 ------------------
__global__ void __launch_bounds__(256)
cvt_split(const float* __restrict__ x, __half* __restrict__ h,
          __half* __restrict__ l, int n)
{
    int i = (blockIdx.x * 256 + threadIdx.x) * 4;
    if (i >= n) return;
    float4 v = *(const float4*)(x + i);
    __half h0 = __float2half_rn(v.x), h1 = __float2half_rn(v.y);
    __half h2 = __float2half_rn(v.z), h3 = __float2half_rn(v.w);
    *(__half2*)(h + i)     = __half2(h0, h1);
    *(__half2*)(h + i + 2) = __half2(h2, h3);
    *(__half2*)(l + i)     = __half2(__float2half_rn(v.x - __half2float(h0)),
                                     __float2half_rn(v.y - __half2float(h1)));
    *(__half2*)(l + i + 2) = __half2(__float2half_rn(v.z - __half2float(h2)),
                                     __float2half_rn(v.w - __half2float(h3)));
}

// concat + split: rows 0-127 = Wfa, 128-255 = Wga, both [128, HID]
__global__ void __launch_bounds__(256)
cvt_concat_split(const float* __restrict__ Wfa, const float* __restrict__ Wga,
                 __half* __restrict__ h, __half* __restrict__ l)
{
    int i = (blockIdx.x * 256 + threadIdx.x) * 4;     // over 256*HID
    int r = i >> 11, c = i & (HID - 1);
    const float* src = (r < 128) ? (Wfa + (size_t)r * HID + c)
                                 : (Wga + (size_t)(r - 128) * HID + c);
    float4 v = *(const float4*)src;
    __half h0 = __float2half_rn(v.x), h1 = __float2half_rn(v.y);
    __half h2 = __float2half_rn(v.z), h3 = __float2half_rn(v.w);
    *(__half2*)(h + i)     = __half2(h0, h1);
    *(__half2*)(h + i + 2) = __half2(h2, h3);
    *(__half2*)(l + i)     = __half2(__float2half_rn(v.x - __half2float(h0)),
                                     __float2half_rn(v.y - __half2float(h1)));
    *(__half2*)(l + i + 2) = __half2(__float2half_rn(v.z - __half2float(h2)),
                                     __float2half_rn(v.w - __half2float(h3)));
}

// ---------------- block reduce over 128 threads ------------------------------
__device__ __forceinline__ float blockReduceSum128(float v) {
    __shared__ float sh[4];
    #pragma unroll
    for (int o = 16; o; o >>= 1) v += __shfl_xor_sync(0xffffffffu, v, o);
    if ((threadIdx.x & 31) == 0) sh[threadIdx.x >> 5] = v;
    __syncthreads();
    return sh[0] + sh[1] + sh[2] + sh[3];
}

// ---------------- causal conv(K=4) + SiLU (+ optional L2 norm) ---------------
// X has row stride NCAT (reads from the fused XCAT at column base per mode)
template<int MODE>  // 0=v, 1=k (l2), 2=q (l2 * dk^-0.5)
__global__ void __launch_bounds__(128)
conv_silu(const float* __restrict__ X, const float* __restrict__ W,
          float* __restrict__ Y)
{
    const int n = blockIdx.x, hh = blockIdx.y, t = threadIdx.x;
    const int c = hh * DK + t;
    const float4 w = *(const float4*)(W + (size_t)c * 4);
    float x0 = (n >= 3) ? X[(size_t)(n-3)*NCAT + c] : 0.f;
    float x1 = (n >= 2) ? X[(size_t)(n-2)*NCAT + c] : 0.f;
    float x2 = (n >= 1) ? X[(size_t)(n-1)*NCAT + c] : 0.f;
    float x3 = X[(size_t)n*NCAT + c];
    float y = x0*w.x + x1*w.y + x2*w.z + x3*w.w;
    y = y / (1.f + expf(-y));
    if (MODE == 0) { Y[(size_t)n*PROJ + c] = y; return; }
    float ss = blockReduceSum128(y * y);
    float sc = rsqrtf(ss + 1e-6f);
    if (MODE == 2) sc *= 0.08838834764831845f;
    Y[(size_t)n*PROJ + c] = y * sc;
}

// ---------------- decay gate: EG = exp(-exp(A_log[h]) * softplus(F + bias)) --
__global__ void decay_kernel(float* __restrict__ F, const float* __restrict__ dtb,
                             const float* __restrict__ A_log)
{
    size_t idx = (size_t)blockIdx.x * blockDim.x + threadIdx.x;
    int c = (int)(idx % PROJ);
    int h = c / DK;
    float x = F[idx] + dtb[c];
    float sp = (x > 20.f) ? x : log1pf(expf(x));
    F[idx] = expf(-expf(A_log[h]) * sp);
}

// ---------------- beta = sigmoid(hidden @ Wb^T) ------------------------------
__global__ void __launch_bounds__(256)
beta_kernel(const float* __restrict__ Xh, const float* __restrict__ Wb,
            float* __restrict__ Beta)
{
    const int warp = threadIdx.x >> 5, lane = threadIdx.x & 31;
    const int n = blockIdx.x;
    const int h = blockIdx.y * 8 + warp;
    const float* x = Xh + (size_t)n * HID;
    const float* w = Wb + (size_t)h * HID;
    float s = 0.f;
    for (int i = lane; i < HID; i += 32) s += x[i] * w[i];
    #pragma unroll
    for (int o = 16; o; o >>= 1) s += __shfl_xor_sync(0xffffffffu, s, o);
    if (lane == 0) Beta[(size_t)n * H + h] = 1.f / (1.f + expf(-s));
}

// ---------------- delta-rule scan v3 ----------------------------------------
__global__ void __launch_bounds__(128)
scan_kernel(const float* __restrict__ Q, const float* __restrict__ Kb,
            const float* __restrict__ Vb, const float* __restrict__ EG,
            const float* __restrict__ Beta, float* __restrict__ O)
{
    const int vb = blockIdx.x, h = blockIdx.y;
    const int t = threadIdx.x;
    const int v = t >> 2, ks = t & 3;
    __shared__ float sk[2][144], sq[2][144], se[2][144];

    unsigned long long S2[16];
    #pragma unroll
    for (int j = 0; j < 16; j++) S2[j] = 0ull;

    const size_t hb = (size_t)h * DK;
    const size_t vboff = hb + (size_t)vb * 32;
    const int slot = (t >> 5) * 36 + (t & 31);

    float rk = Kb[hb + t], rq = Q[hb + t], re = EG[hb + t];
    float rv = Vb[vboff + v], rb = Beta[h];
    sk[0][slot] = rk; sq[0][slot] = rq; se[0][slot] = re;
    float curv = rv, curb = rb;

    rk = Kb[PROJ + hb + t]; rq = Q[PROJ + hb + t]; re = EG[PROJ + hb + t];
    rv = Vb[PROJ + vboff + v]; rb = Beta[H + h];
    __syncthreads();

    for (int n = 0; n < N_TOK; n++) {
        const int cur = n & 1;
        float nv = rv, nb = rb;
        if (n + 1 < N_TOK) {
            sk[cur ^ 1][slot] = rk; sq[cur ^ 1][slot] = rq; se[cur ^ 1][slot] = re;
        }
        if (n + 2 < N_TOK) {
            size_t b = (size_t)(n + 2) * PROJ;
            rk = Kb[b + hb + t]; rq = Q[b + hb + t]; re = EG[b + hb + t];
            rv = Vb[b + vboff + v]; rb = Beta[(size_t)(n + 2) * H + h];
        }

        const float* kp = &sk[cur][ks * 36];
        const float* ep = &se[cur][ks * 36];
        const float* qp = &sq[cur][ks * 36];

        unsigned long long k2[16];
        unsigned long long kva = 0ull, kvb = 0ull, kvc = 0ull, kvd = 0ull;
        #pragma unroll
        for (int j = 0; j < 16; j += 4) {
            k2[j]   = *(const unsigned long long*)(kp + 2*j);
            k2[j+1] = *(const unsigned long long*)(kp + 2*j + 2);
            k2[j+2] = *(const unsigned long long*)(kp + 2*j + 4);
            k2[j+3] = *(const unsigned long long*)(kp + 2*j + 6);
            unsigned long long e0 = *(const unsigned long long*)(ep + 2*j);
            unsigned long long e1 = *(const unsigned long long*)(ep + 2*j + 2);
            unsigned long long e2 = *(const unsigned long long*)(ep + 2*j + 4);
            unsigned long long e3 = *(const unsigned long long*)(ep + 2*j + 6);
            MUL2(S2[j],   S2[j],   e0);  FMA2(kva, k2[j],   S2[j],   kva);
            MUL2(S2[j+1], S2[j+1], e1);  FMA2(kvb, k2[j+1], S2[j+1], kvb);
            MUL2(S2[j+2], S2[j+2], e2);  FMA2(kvc, k2[j+2], S2[j+2], kvc);
            MUL2(S2[j+3], S2[j+3], e3);  FMA2(kvd, k2[j+3], S2[j+3], kvd);
        }
        float kv = sum2(kva) + sum2(kvb) + (sum2(kvc) + sum2(kvd));
        kv += __shfl_xor_sync(0xffffffffu, kv, 1);
        kv += __shfl_xor_sync(0xffffffffu, kv, 2);
        float delta = (curv - kv) * curb;
        unsigned long long d2 = pack2(delta, delta);

        unsigned long long oa = 0ull, ob = 0ull, oc = 0ull, od = 0ull;
        #pragma unroll
        for (int j = 0; j < 16; j += 4) {
            unsigned long long q0 = *(const unsigned long long*)(qp + 2*j);
            unsigned long long q1 = *(const unsigned long long*)(qp + 2*j + 2);
            unsigned long long q2 = *(const unsigned long long*)(qp + 2*j + 4);
            unsigned long long q3 = *(const unsigned long long*)(qp + 2*j + 6);
            FMA2(S2[j],   k2[j],   d2, S2[j]);    FMA2(oa, q0, S2[j],   oa);
            FMA2(S2[j+1], k2[j+1], d2, S2[j+1]);  FMA2(ob, q1, S2[j+1], ob);
            FMA2(S2[j+2], k2[j+2], d2, S2[j+2]);  FMA2(oc, q2, S2[j+2], oc);
            FMA2(S2[j+3], k2[j+3], d2, S2[j+3]);  FMA2(od, q3, S2[j+3], od);
        }
        float op = sum2(oa) + sum2(ob) + (sum2(oc) + sum2(od));
        op += __shfl_xor_sync(0xffffffffu, op, 1);
        op += __shfl_xor_sync(0xffffffffu, op, 2);
        if (ks == 0) O[(size_t)n * PROJ + vboff + v] = op;

        curv = nv; curb = nb;
        __syncthreads();
    }
}

// ---------------- gated RMSNorm -> fp16 --------------------------------------
__global__ void __launch_bounds__(128)
norm_gate(const float* __restrict__ O, const float* __restrict__ Gate,
          const float* __restrict__ onw, __half* __restrict__ oh)
{
    const int n = blockIdx.x, hh = blockIdx.y, t = threadIdx.x;
    const size_t idx = (size_t)n * PROJ + hh * DK + t;
    float o = O[idx];
    float ms = blockReduceSum128(o * o) * (1.f / DK);
    float r = o * rsqrtf(ms + 1e-5f);
    float g = Gate[idx];
    float y = r * onw[t] / (1.f + expf(-g));
    oh[idx] = __float2half_rn(y);
}

// ---------------- launch -----------------------------------------------------
extern "C" void kernel_launch(void* const* d_in, const int* in_sizes, int n_in,
                              void* d_out, int out_size)
{
    const float* hs      = (const float*)d_in[0];
    const float* Wq      = (const float*)d_in[1];
    const float* Wk      = (const float*)d_in[2];
    const float* Wv      = (const float*)d_in[3];
    const float* conv_q  = (const float*)d_in[4];
    const float* conv_k  = (const float*)d_in[5];
    const float* conv_v  = (const float*)d_in[6];
    const float* Wfa     = (const float*)d_in[7];
    const float* Wfb     = (const float*)d_in[8];
    const float* dt_bias = (const float*)d_in[9];
    const float* Wb      = (const float*)d_in[10];
    const float* A_log   = (const float*)d_in[11];
    const float* Wga     = (const float*)d_in[12];
    const float* Wgb     = (const float*)d_in[13];
    const float* onorm_w = (const float*)d_in[14];
    const float* Wo      = (const float*)d_in[15];
    float* out = (float*)d_out;

    float *pXCAT, *pXQ, *pQ, *pK, *pV, *pEG, *pO, *pBeta;
    cudaGetSymbolAddress((void**)&pXCAT, g_XCAT);
    cudaGetSymbolAddress((void**)&pXQ, g_XQ);
    cudaGetSymbolAddress((void**)&pQ,  g_Q);
    cudaGetSymbolAddress((void**)&pK,  g_Kb);
    cudaGetSymbolAddress((void**)&pV,  g_Vb);
    cudaGetSymbolAddress((void**)&pEG, g_EG);
    cudaGetSymbolAddress((void**)&pO,  g_O);
    cudaGetSymbolAddress((void**)&pBeta, g_beta);

    __half *hsH,*WcatH,*WcatL,*WoH,*WoL,*WfbH,*WfbL,*WgbH,*WgbL,*FGH,*ONH;
    cudaGetSymbolAddress((void**)&hsH, s_hsH);
    cudaGetSymbolAddress((void**)&WcatH, s_WcatH);
    cudaGetSymbolAddress((void**)&WcatL, s_WcatL);
    cudaGetSymbolAddress((void**)&WoH, s_WoH);  cudaGetSymbolAddress((void**)&WoL, s_WoL);
    cudaGetSymbolAddress((void**)&WfbH, s_WfbH);cudaGetSymbolAddress((void**)&WfbL, s_WfbL);
    cudaGetSymbolAddress((void**)&WgbH, s_WgbH);cudaGetSymbolAddress((void**)&WgbL, s_WgbL);
    cudaGetSymbolAddress((void**)&FGH, s_FGH);
    cudaGetSymbolAddress((void**)&ONH, s_ONH);

    cudaFuncSetAttribute(mma_gemm, cudaFuncAttributeMaxDynamicSharedMemorySize, GEMM_SMEM);

    auto grid4 = [](size_t n) { return dim3((unsigned)((n / 4 + 255) / 256)); };

    const size_t WSZ = (size_t)PROJ * HID;
    const dim3 gCat(NCAT/128, N_TOK/128);   // 98 x 16
    const dim3 gBig(PROJ/128, N_TOK/128);   // 32 x 16
    const dim3 gOut(HID/128,  N_TOK/128);   // 16 x 16
    const dim3 gCh (N_TOK, H);

    // 1-5: conversions into the fused weight concat
    cvt_half<<<grid4((size_t)N_TOK*HID), 256>>>(hs, hsH, N_TOK*HID);
    cvt_split<<<grid4(WSZ), 256>>>(Wq, WcatH,           WcatL,           (int)WSZ);
    cvt_split<<<grid4(WSZ), 256>>>(Wk, WcatH + WSZ,     WcatL + WSZ,     (int)WSZ);
    cvt_split<<<grid4(WSZ), 256>>>(Wv, WcatH + 2*WSZ,   WcatL + 2*WSZ,   (int)WSZ);
    cvt_concat_split<<<grid4((size_t)256*HID), 256>>>(Wfa, Wga, WcatH + 3*WSZ, WcatL + 3*WSZ);

    // 6: fused QKV+FG projection GEMM (profiled slot)
    mma_gemm<<<gCat, 256, GEMM_SMEM>>>(hsH, WcatH, WcatL, pXCAT, HID, HID, HID, NCAT);

    // remaining weight conversions
    cvt_split<<<grid4((size_t)HID*PROJ), 256>>>(Wo, WoH, WoL, HID*PROJ);
    cvt_split<<<grid4((size_t)PROJ*DK), 256>>>(Wfb, WfbH, WfbL, PROJ*DK);
    cvt_split<<<grid4((size_t)PROJ*DK), 256>>>(Wgb, WgbH, WgbL, PROJ*DK);

    // conv + silu (+ norms) reading from XCAT columns
    conv_silu<2><<<gCh, 128>>>(pXCAT,            conv_q, pQ);
    conv_silu<1><<<gCh, 128>>>(pXCAT + PROJ,     conv_k, pK);
    conv_silu<0><<<gCh, 128>>>(pXCAT + 2*PROJ,   conv_v, pV);

    // FG -> fp16 (strided extract from XCAT)
    cvt_fg<<<grid4((size_t)N_TOK*256), 256>>>(pXCAT, FGH);

    // decay chain: EG = FG[:, :128] @ Wfb^T -> exp(g)
    mma_gemm<<<gBig, 256, GEMM_SMEM>>>(FGH, WfbH, WfbL, pEG, DK, 256, DK, PROJ);
    decay_kernel<<<(N_TOK*(size_t)PROJ)/256, 256>>>(pEG, dt_bias, A_log);

    // gate: Gate = FG[:, 128:] @ Wgb^T
    mma_gemm<<<gBig, 256, GEMM_SMEM>>>(FGH + 128, WgbH, WgbL, pXQ, DK, 256, DK, PROJ);

    // beta
    beta_kernel<<<dim3(N_TOK, 4), 256>>>(hs, Wb, pBeta);

    // recurrent delta-rule scan
    scan_kernel<<<dim3(4, H), 128>>>(pQ, pK, pV, pEG, pBeta, pO);

    // gated RMSNorm -> fp16
    norm_gate<<<gCh, 128>>>(pO, pXQ, onorm_w, ONH);

    // output projection
    mma_gemm<<<gOut, 256, GEMM_SMEM>>>(ONH, WoH, WoL, out, PROJ, PROJ, PROJ, HID);
}